// round 1
// baseline (speedup 1.0000x reference)
#include <cuda_runtime.h>
#include <cuda_bf16.h>
#include <math.h>

// ---------------- problem-size bounds (N=100000, E=1600000) ----------------
#define MAXN 102400
#define MAXE 1605632

// ---------------- device scratch (no allocation allowed) -------------------
__device__ float g_dinv[MAXN];            // deg (pass1) then d^{-1/2}
__device__ int   g_cnt[MAXN];             // per-row edge count
__device__ int   g_fill[MAXN];            // scatter fill cursor
__device__ int   g_rowptr[MAXN + 1];      // CSR row pointer
__device__ int   g_bsums[256];            // scan block sums
__device__ int   g_boffs[256];            // scan block offsets
__device__ int   g_cols[MAXE];            // CSR col indices
__device__ float g_norm[MAXE];            // CSR normalized edge weights
__device__ float g_xp[MAXN * 32];         // x@W1_0 (cols 0..15) | x@W1_1 (16..31)
__device__ float g_h[MAXN * 16];          // hidden after relu
__device__ float g_hp[MAXN * 64];         // h@W2_0 (0..31) | h@W2_1 (32..63)
__device__ int   g_is64;                  // edge_index dtype flag

// ---------------- edge index dtype detection --------------------------------
__global__ void k_detect(const int* __restrict__ w) {
    if (threadIdx.x == 0 && blockIdx.x == 0) {
        // If dtype is int64 (little-endian, values in [0, 2^31)), every odd
        // 32-bit word among the first 128 words is zero. If int32, odd words
        // are random node indices -> virtually impossible to all be zero.
        int is64 = 1;
        #pragma unroll
        for (int i = 1; i < 128; i += 2)
            if (w[i] != 0) { is64 = 0; break; }
        g_is64 = is64;
    }
}

__device__ __forceinline__ int eidx_at(const void* p, long i) {
    if (g_is64) return (int)((const long long*)p)[i];
    return ((const int*)p)[i];
}

// ---------------- init -------------------------------------------------------
__global__ void k_init(int N) {
    int i = blockIdx.x * blockDim.x + threadIdx.x;
    if (i < N) {
        g_dinv[i] = 0.f;
        g_cnt[i]  = 0;
        g_fill[i] = 0;
    }
}

// ---------------- pass 1: degree (weighted) + counts -------------------------
__global__ void k_deg(const void* __restrict__ ei, const float* __restrict__ ew, int E) {
    int e = blockIdx.x * blockDim.x + threadIdx.x;
    if (e < E) {
        int r = eidx_at(ei, e);               // row = edge_index[0][e]
        atomicAdd(&g_dinv[r], ew[e]);
        atomicAdd(&g_cnt[r], 1);
    }
}

__global__ void k_dinv(int N) {
    int i = blockIdx.x * blockDim.x + threadIdx.x;
    if (i < N) {
        float d = g_dinv[i];
        g_dinv[i] = (d > 0.f) ? rsqrtf(d) : 0.f;
    }
}

// ---------------- exclusive scan of g_cnt -> g_rowptr ------------------------
// phase A: per-block (2048 elems) local exclusive scan + block sums
__global__ void k_scan_local(int N) {
    __shared__ int warpSums[32];
    int t = threadIdx.x;
    int base = blockIdx.x * 2048;
    int i0 = base + 2 * t, i1 = i0 + 1;
    int v0 = (i0 < N) ? g_cnt[i0] : 0;
    int v1 = (i1 < N) ? g_cnt[i1] : 0;
    int s = v0 + v1;
    int lane = t & 31, wid = t >> 5;
    int incl = s;
    #pragma unroll
    for (int d = 1; d < 32; d <<= 1) {
        int n = __shfl_up_sync(0xffffffffu, incl, d);
        if (lane >= d) incl += n;
    }
    if (lane == 31) warpSums[wid] = incl;
    __syncthreads();
    if (wid == 0) {
        int ws = warpSums[lane];
        int wi = ws;
        #pragma unroll
        for (int d = 1; d < 32; d <<= 1) {
            int n = __shfl_up_sync(0xffffffffu, wi, d);
            if (lane >= d) wi += n;
        }
        warpSums[lane] = wi - ws;   // exclusive warp offsets
    }
    __syncthreads();
    int excl = warpSums[wid] + incl - s;  // exclusive prefix within block
    if (i0 < N) g_rowptr[i0] = excl;
    if (i1 < N) g_rowptr[i1] = excl + v0;
    if (t == 1023) g_bsums[blockIdx.x] = warpSums[wid] + incl; // block total
}

// phase B: serial scan of block sums (NB <= 64)
__global__ void k_scan_bsums(int NB) {
    if (threadIdx.x == 0 && blockIdx.x == 0) {
        int run = 0;
        for (int b = 0; b < NB; b++) {
            int t = g_bsums[b];
            g_boffs[b] = run;
            run += t;
        }
    }
}

// phase C: add block offsets, write sentinel
__global__ void k_scan_add(int N, int E) {
    int i = blockIdx.x * blockDim.x + threadIdx.x;
    if (i < N) g_rowptr[i] += g_boffs[i >> 11];
    if (i == 0) g_rowptr[N] = E;
}

// ---------------- pass 2: scatter edges into CSR -----------------------------
__global__ void k_scatter(const void* __restrict__ ei, const float* __restrict__ ew, int E) {
    int e = blockIdx.x * blockDim.x + threadIdx.x;
    if (e < E) {
        int r = eidx_at(ei, e);
        int c = eidx_at(ei, (long)E + e);
        float nv = g_dinv[r] * ew[e] * g_dinv[c];
        int p = g_rowptr[r] + atomicAdd(&g_fill[r], 1);
        g_cols[p] = c;
        g_norm[p] = nv;
    }
}

// ---------------- GEMM1: xp = [x@W1_0 | x@W1_1]  (N x 128 -> N x 32) --------
// 4 nodes per warp, 8 warps/block -> 32 nodes/block. W staged to shared.
__global__ void k_gemm1(const float* __restrict__ x,
                        const float* __restrict__ W0,
                        const float* __restrict__ W1, int N) {
    __shared__ float  Wsh[128 * 32];       // 16 KB: Wsh[k*32 + j]
    __shared__ float4 xs[8][4][32];        // 16 KB: per-warp 4 node rows
    int t = threadIdx.x;
    for (int i = t; i < 128 * 16; i += 256) {
        int k = i >> 4, j = i & 15;
        Wsh[k * 32 + j]      = W0[i];
        Wsh[k * 32 + 16 + j] = W1[i];
    }
    __syncthreads();
    int warp = t >> 5, lane = t & 31;
    int base = (blockIdx.x * 8 + warp) * 4;
    #pragma unroll
    for (int n = 0; n < 4; n++) {
        int node = base + n;
        float4 v = make_float4(0.f, 0.f, 0.f, 0.f);
        if (node < N) v = ((const float4*)(x + (size_t)node * 128))[lane];
        xs[warp][n][lane] = v;
    }
    __syncwarp();
    float a0 = 0.f, a1 = 0.f, a2 = 0.f, a3 = 0.f;
    #pragma unroll
    for (int k4 = 0; k4 < 32; k4++) {
        float w0 = Wsh[(k4 * 4 + 0) * 32 + lane];
        float w1 = Wsh[(k4 * 4 + 1) * 32 + lane];
        float w2 = Wsh[(k4 * 4 + 2) * 32 + lane];
        float w3 = Wsh[(k4 * 4 + 3) * 32 + lane];
        float4 b0 = xs[warp][0][k4];
        float4 b1 = xs[warp][1][k4];
        float4 b2 = xs[warp][2][k4];
        float4 b3 = xs[warp][3][k4];
        a0 = fmaf(b0.x, w0, fmaf(b0.y, w1, fmaf(b0.z, w2, fmaf(b0.w, w3, a0))));
        a1 = fmaf(b1.x, w0, fmaf(b1.y, w1, fmaf(b1.z, w2, fmaf(b1.w, w3, a1))));
        a2 = fmaf(b2.x, w0, fmaf(b2.y, w1, fmaf(b2.z, w2, fmaf(b2.w, w3, a2))));
        a3 = fmaf(b3.x, w0, fmaf(b3.y, w1, fmaf(b3.z, w2, fmaf(b3.w, w3, a3))));
    }
    if (base + 0 < N) g_xp[(size_t)(base + 0) * 32 + lane] = a0;
    if (base + 1 < N) g_xp[(size_t)(base + 1) * 32 + lane] = a1;
    if (base + 2 < N) g_xp[(size_t)(base + 2) * 32 + lane] = a2;
    if (base + 3 < N) g_xp[(size_t)(base + 3) * 32 + lane] = a3;
}

// ---------------- layer1: h = relu(xp0 + agg(xp1) - xp1 + b1) ----------------
// one warp per row; lanes: feature f = lane&15, edge slot = lane>>4 (2-way ILP)
__global__ void k_layer1(const float* __restrict__ b1, int N) {
    int t = blockIdx.x * blockDim.x + threadIdx.x;
    int row = t >> 5;
    if (row >= N) return;
    int lane = t & 31;
    int f = lane & 15, slot = lane >> 4;
    int s = g_rowptr[row], e = g_rowptr[row + 1];
    float acc = 0.f;
    for (int p = s + slot; p < e; p += 2) {
        int c = g_cols[p];
        float nv = g_norm[p];
        acc = fmaf(nv, g_xp[(size_t)c * 32 + 16 + f], acc);
    }
    acc += __shfl_xor_sync(0xffffffffu, acc, 16);
    if (lane < 16) {
        float v = g_xp[(size_t)row * 32 + f] + acc
                - g_xp[(size_t)row * 32 + 16 + f] + b1[f];
        g_h[(size_t)row * 16 + f] = v > 0.f ? v : 0.f;
    }
}

// ---------------- GEMM2: hp = [h@W2_0 | h@W2_1] (N x 16 -> N x 64) ----------
__global__ void k_gemm2(const float* __restrict__ W20,
                        const float* __restrict__ W21, int N) {
    __shared__ float Wsh[16 * 64];   // 4 KB: Wsh[k*64 + j]
    int t = threadIdx.x;
    for (int i = t; i < 16 * 32; i += 256) {
        int k = i >> 5, j = i & 31;
        Wsh[k * 64 + j]      = W20[i];
        Wsh[k * 64 + 32 + j] = W21[i];
    }
    __syncthreads();
    int warp = t >> 5, lane = t & 31;
    int node = blockIdx.x * 8 + warp;
    if (node >= N) return;
    float hv = (lane < 16) ? g_h[(size_t)node * 16 + lane] : 0.f;
    float a0 = 0.f, a1 = 0.f;
    #pragma unroll
    for (int k = 0; k < 16; k++) {
        float hk = __shfl_sync(0xffffffffu, hv, k);
        a0 = fmaf(hk, Wsh[k * 64 + lane], a0);
        a1 = fmaf(hk, Wsh[k * 64 + 32 + lane], a1);
    }
    g_hp[(size_t)node * 64 + lane]      = a0;
    g_hp[(size_t)node * 64 + 32 + lane] = a1;
}

// ---------------- layer2 + log_softmax ---------------------------------------
// one warp per row; lane = class c in [0,32)
__global__ void k_layer2(const float* __restrict__ b2, float* __restrict__ out, int N) {
    int t = blockIdx.x * blockDim.x + threadIdx.x;
    int row = t >> 5;
    if (row >= N) return;
    int lane = t & 31;
    int s = g_rowptr[row], e = g_rowptr[row + 1];
    float acc = 0.f;
    for (int p = s; p < e; p++) {
        int c = g_cols[p];
        float nv = g_norm[p];
        acc = fmaf(nv, g_hp[(size_t)c * 64 + 32 + lane], acc);
    }
    float val = g_hp[(size_t)row * 64 + lane] + acc
              - g_hp[(size_t)row * 64 + 32 + lane] + b2[lane];
    // log_softmax over 32 lanes
    float m = val;
    #pragma unroll
    for (int d = 16; d; d >>= 1) m = fmaxf(m, __shfl_xor_sync(0xffffffffu, m, d));
    float ex = expf(val - m);
    float sum = ex;
    #pragma unroll
    for (int d = 16; d; d >>= 1) sum += __shfl_xor_sync(0xffffffffu, sum, d);
    out[(size_t)row * 32 + lane] = val - m - logf(sum);
}

// ---------------- launcher ----------------------------------------------------
extern "C" void kernel_launch(void* const* d_in, const int* in_sizes, int n_in,
                              void* d_out, int out_size) {
    const float* x   = (const float*)d_in[0];
    const void*  ei  = d_in[1];
    const float* ew  = (const float*)d_in[2];
    const float* W10 = (const float*)d_in[3];
    const float* W11 = (const float*)d_in[4];
    const float* b1  = (const float*)d_in[5];
    const float* W20 = (const float*)d_in[6];
    const float* W21 = (const float*)d_in[7];
    const float* b2  = (const float*)d_in[8];
    float* out = (float*)d_out;

    int N = in_sizes[0] / 128;
    int E = in_sizes[2];

    k_detect<<<1, 32>>>((const int*)ei);
    k_init<<<(N + 255) / 256, 256>>>(N);
    k_deg<<<(E + 255) / 256, 256>>>(ei, ew, E);
    k_dinv<<<(N + 255) / 256, 256>>>(N);

    int NB = (N + 2047) / 2048;
    k_scan_local<<<NB, 1024>>>(N);
    k_scan_bsums<<<1, 32>>>(NB);
    k_scan_add<<<(N + 255) / 256, 256>>>(N, E);

    k_scatter<<<(E + 255) / 256, 256>>>(ei, ew, E);

    k_gemm1<<<(N + 31) / 32, 256>>>(x, W10, W11, N);
    k_layer1<<<(N + 7) / 8, 256>>>(b1, N);
    k_gemm2<<<(N + 7) / 8, 256>>>(W20, W21, N);
    k_layer2<<<(N + 7) / 8, 256>>>(b2, out, N);
}

// round 2
// speedup vs baseline: 1.1498x; 1.1498x over previous
#include <cuda_runtime.h>
#include <math.h>

#define MAXN 102400
#define MAXE 1605632

// ---------------- device scratch --------------------------------------------
__device__ int    g_cnt[MAXN];
__device__ int    g_rowptr[MAXN];        // starts after scan; ends after scatter
__device__ int    g_bsums[64];
__device__ int    g_boffs[64];
__device__ int2   g_csr[MAXE];           // (col, ew bits)
__device__ float4 g_A4[MAXN * 4];        // xp0 - xp1  (per node, 16 floats)
__device__ float4 g_B4[MAXN * 4];        // dinv * xp1 (gather target, layer 1)
__device__ float4 g_h4[MAXN * 4];        // h = relu(...)
__device__ float4 g_hs4[MAXN * 4];       // dinv * h   (gather target, layer 2)
__device__ float  g_dinv[MAXN];
__device__ int    g_is64;

// ---------------- init + edge-index dtype detection -------------------------
__global__ void k_init(const int* __restrict__ w, int N) {
    int i = blockIdx.x * blockDim.x + threadIdx.x;
    if (i < N) g_cnt[i] = 0;
    if (blockIdx.x == 0 && threadIdx.x == 0) {
        // int64 nonneg < 2^31 -> every odd 32-bit word of the first 128 is 0
        int is64 = 1;
        #pragma unroll
        for (int j = 1; j < 128; j += 2)
            if (w[j] != 0) { is64 = 0; break; }
        g_is64 = is64;
    }
}

__device__ __forceinline__ int eidx_at(const void* p, long i) {
    if (g_is64) return (int)((const long long*)p)[i];
    return ((const int*)p)[i];
}

// ---------------- pass 1: per-row edge counts --------------------------------
__global__ void k_cnt(const void* __restrict__ ei, int E) {
    int e = blockIdx.x * blockDim.x + threadIdx.x;
    if (e < E) atomicAdd(&g_cnt[eidx_at(ei, e)], 1);
}

// ---------------- exclusive scan of g_cnt -> g_rowptr (starts) ---------------
__global__ void k_scan_local(int N) {
    __shared__ int warpSums[32];
    int t = threadIdx.x;
    int base = blockIdx.x * 2048;
    int i0 = base + 2 * t, i1 = i0 + 1;
    int v0 = (i0 < N) ? g_cnt[i0] : 0;
    int v1 = (i1 < N) ? g_cnt[i1] : 0;
    int s = v0 + v1;
    int lane = t & 31, wid = t >> 5;
    int incl = s;
    #pragma unroll
    for (int d = 1; d < 32; d <<= 1) {
        int n = __shfl_up_sync(0xffffffffu, incl, d);
        if (lane >= d) incl += n;
    }
    if (lane == 31) warpSums[wid] = incl;
    __syncthreads();
    if (wid == 0) {
        int ws = warpSums[lane];
        int wi = ws;
        #pragma unroll
        for (int d = 1; d < 32; d <<= 1) {
            int n = __shfl_up_sync(0xffffffffu, wi, d);
            if (lane >= d) wi += n;
        }
        warpSums[lane] = wi - ws;
    }
    __syncthreads();
    int excl = warpSums[wid] + incl - s;
    if (i0 < N) g_rowptr[i0] = excl;
    if (i1 < N) g_rowptr[i1] = excl + v0;
    if (t == 1023) g_bsums[blockIdx.x] = warpSums[wid] + incl;
}

__global__ void k_scan_bsums(int NB) {
    if (threadIdx.x == 0 && blockIdx.x == 0) {
        int run = 0;
        for (int b = 0; b < NB; b++) { int t = g_bsums[b]; g_boffs[b] = run; run += t; }
    }
}

__global__ void k_scan_add(int N) {
    int i = blockIdx.x * blockDim.x + threadIdx.x;
    if (i < N) g_rowptr[i] += g_boffs[i >> 11];
}

// ---------------- pass 2: scatter into CSR; rowptr becomes ENDS --------------
__global__ void k_scatter(const void* __restrict__ ei, const float* __restrict__ ew, int E) {
    int e = blockIdx.x * blockDim.x + threadIdx.x;
    if (e < E) {
        int r = eidx_at(ei, e);
        int c = eidx_at(ei, (long)E + e);
        int p = atomicAdd(&g_rowptr[r], 1);
        g_csr[p] = make_int2(c, __float_as_int(ew[e]));
    }
}

// ---------------- GEMM1 + degree/dinv ----------------------------------------
// 8 warps x 4 nodes. Writes A = x@W0 - x@W1, B = dinv * (x@W1), g_dinv.
__global__ void k_gemm1(const float* __restrict__ x,
                        const float* __restrict__ W0,
                        const float* __restrict__ W1, int N) {
    __shared__ float  Wsh[128 * 32];
    __shared__ float4 xs[8][4][32];
    __shared__ float  dvs[8][4];
    int t = threadIdx.x;
    for (int i = t; i < 128 * 16; i += 256) {
        int k = i >> 4, j = i & 15;
        Wsh[k * 32 + j]      = W0[i];
        Wsh[k * 32 + 16 + j] = W1[i];
    }
    int warp = t >> 5, lane = t & 31;
    int base = (blockIdx.x * 8 + warp) * 4;

    // weighted degree from CSR: 8 lanes per node
    {
        int g = lane >> 3, l8 = lane & 7;
        int node = base + g;
        float dsum = 0.f;
        if (node < N) {
            int s = node ? g_rowptr[node - 1] : 0;
            int e = g_rowptr[node];
            for (int p = s + l8; p < e; p += 8)
                dsum += __int_as_float(g_csr[p].y);
        }
        dsum += __shfl_xor_sync(0xffffffffu, dsum, 1);
        dsum += __shfl_xor_sync(0xffffffffu, dsum, 2);
        dsum += __shfl_xor_sync(0xffffffffu, dsum, 4);
        float dv = (dsum > 0.f) ? rsqrtf(dsum) : 0.f;
        if (l8 == 0 && node < N) { g_dinv[node] = dv; dvs[warp][g] = dv; }
    }

    #pragma unroll
    for (int n = 0; n < 4; n++) {
        int nd = base + n;
        float4 v = make_float4(0.f, 0.f, 0.f, 0.f);
        if (nd < N) v = ((const float4*)(x + (size_t)nd * 128))[lane];
        xs[warp][n][lane] = v;
    }
    __syncthreads();

    float a0 = 0.f, a1 = 0.f, a2 = 0.f, a3 = 0.f;
    #pragma unroll
    for (int k4 = 0; k4 < 32; k4++) {
        float w0 = Wsh[(k4 * 4 + 0) * 32 + lane];
        float w1 = Wsh[(k4 * 4 + 1) * 32 + lane];
        float w2 = Wsh[(k4 * 4 + 2) * 32 + lane];
        float w3 = Wsh[(k4 * 4 + 3) * 32 + lane];
        float4 b0 = xs[warp][0][k4];
        float4 b1 = xs[warp][1][k4];
        float4 b2 = xs[warp][2][k4];
        float4 b3 = xs[warp][3][k4];
        a0 = fmaf(b0.x, w0, fmaf(b0.y, w1, fmaf(b0.z, w2, fmaf(b0.w, w3, a0))));
        a1 = fmaf(b1.x, w0, fmaf(b1.y, w1, fmaf(b1.z, w2, fmaf(b1.w, w3, a1))));
        a2 = fmaf(b2.x, w0, fmaf(b2.y, w1, fmaf(b2.z, w2, fmaf(b2.w, w3, a2))));
        a3 = fmaf(b3.x, w0, fmaf(b3.y, w1, fmaf(b3.z, w2, fmaf(b3.w, w3, a3))));
    }

    float* A = (float*)g_A4;
    float* B = (float*)g_B4;
    float acc[4] = {a0, a1, a2, a3};
    #pragma unroll
    for (int n = 0; n < 4; n++) {
        int nd = base + n;
        float a = acc[n];
        float o = __shfl_xor_sync(0xffffffffu, a, 16);  // partner half
        if (nd < N) {
            float dv = dvs[warp][n];
            if (lane < 16) A[(size_t)nd * 16 + lane] = a - o;         // xp0 - xp1
            else           B[(size_t)nd * 16 + (lane - 16)] = dv * a; // dinv*xp1
        }
    }
}

// ---------------- layer1: h = relu(A + dinv*agg(B) + b1) ---------------------
// warp/row; q=lane&3 float4 index, slot=lane>>2 -> 8 edges per iteration
__global__ void k_layer1(const float* __restrict__ b1, int N) {
    int t = blockIdx.x * blockDim.x + threadIdx.x;
    int row = t >> 5;
    if (row >= N) return;
    int lane = t & 31, q = lane & 3, slot = lane >> 2;
    int s = row ? g_rowptr[row - 1] : 0;
    int e = g_rowptr[row];
    float4 acc = make_float4(0.f, 0.f, 0.f, 0.f);
    for (int p = s + slot; p < e; p += 8) {
        int2 ce = g_csr[p];
        float nv = __int_as_float(ce.y);
        float4 v = g_B4[(size_t)ce.x * 4 + q];
        acc.x = fmaf(nv, v.x, acc.x);
        acc.y = fmaf(nv, v.y, acc.y);
        acc.z = fmaf(nv, v.z, acc.z);
        acc.w = fmaf(nv, v.w, acc.w);
    }
    #pragma unroll
    for (int d = 4; d < 32; d <<= 1) {
        acc.x += __shfl_xor_sync(0xffffffffu, acc.x, d);
        acc.y += __shfl_xor_sync(0xffffffffu, acc.y, d);
        acc.z += __shfl_xor_sync(0xffffffffu, acc.z, d);
        acc.w += __shfl_xor_sync(0xffffffffu, acc.w, d);
    }
    if (lane < 4) {
        float dv = g_dinv[row];
        float4 A  = g_A4[(size_t)row * 4 + lane];
        float4 bb = ((const float4*)b1)[lane];
        float4 h;
        h.x = fmaxf(A.x + dv * acc.x + bb.x, 0.f);
        h.y = fmaxf(A.y + dv * acc.y + bb.y, 0.f);
        h.z = fmaxf(A.z + dv * acc.z + bb.z, 0.f);
        h.w = fmaxf(A.w + dv * acc.w + bb.w, 0.f);
        g_h4[(size_t)row * 4 + lane]  = h;
        g_hs4[(size_t)row * 4 + lane] = make_float4(dv * h.x, dv * h.y, dv * h.z, dv * h.w);
    }
}

// ---------------- layer2: agg(hs) + dual GEMV + log_softmax ------------------
__global__ void k_layer2(const float* __restrict__ W20,
                         const float* __restrict__ W21,
                         const float* __restrict__ b2,
                         float* __restrict__ out, int N) {
    __shared__ float Wd[16 * 32];   // W20 - W21
    __shared__ float Wb[16 * 32];   // W21
    int t = threadIdx.x;
    for (int i = t; i < 512; i += blockDim.x) {
        float w1v = W21[i];
        Wd[i] = W20[i] - w1v;
        Wb[i] = w1v;
    }
    __syncthreads();
    int gt = blockIdx.x * blockDim.x + t;
    int row = gt >> 5;
    if (row >= N) return;
    int lane = t & 31, q = lane & 3, slot = lane >> 2;
    int s = row ? g_rowptr[row - 1] : 0;
    int e = g_rowptr[row];
    float4 acc = make_float4(0.f, 0.f, 0.f, 0.f);
    for (int p = s + slot; p < e; p += 8) {
        int2 ce = g_csr[p];
        float nv = __int_as_float(ce.y);
        float4 v = g_hs4[(size_t)ce.x * 4 + q];
        acc.x = fmaf(nv, v.x, acc.x);
        acc.y = fmaf(nv, v.y, acc.y);
        acc.z = fmaf(nv, v.z, acc.z);
        acc.w = fmaf(nv, v.w, acc.w);
    }
    #pragma unroll
    for (int d = 4; d < 32; d <<= 1) {
        acc.x += __shfl_xor_sync(0xffffffffu, acc.x, d);
        acc.y += __shfl_xor_sync(0xffffffffu, acc.y, d);
        acc.z += __shfl_xor_sync(0xffffffffu, acc.z, d);
        acc.w += __shfl_xor_sync(0xffffffffu, acc.w, d);
    }
    float4 hv = make_float4(0.f, 0.f, 0.f, 0.f);
    if (lane < 4) hv = g_h4[(size_t)row * 4 + lane];
    float dv = g_dinv[row];

    float sh = 0.f, sa = 0.f;
    #pragma unroll
    for (int f = 0; f < 16; f++) {
        int src = f >> 2;
        float ch, ca;
        if ((f & 3) == 0)      { ch = hv.x; ca = acc.x; }
        else if ((f & 3) == 1) { ch = hv.y; ca = acc.y; }
        else if ((f & 3) == 2) { ch = hv.z; ca = acc.z; }
        else                   { ch = hv.w; ca = acc.w; }
        float hf = __shfl_sync(0xffffffffu, ch, src);
        float af = __shfl_sync(0xffffffffu, ca, src);
        sh = fmaf(hf, Wd[f * 32 + lane], sh);
        sa = fmaf(af, Wb[f * 32 + lane], sa);
    }
    float val = sh + dv * sa + __ldg(&b2[lane]);

    float m = val;
    #pragma unroll
    for (int d = 16; d; d >>= 1) m = fmaxf(m, __shfl_xor_sync(0xffffffffu, m, d));
    float ex = __expf(val - m);
    float sum = ex;
    #pragma unroll
    for (int d = 16; d; d >>= 1) sum += __shfl_xor_sync(0xffffffffu, sum, d);
    out[(size_t)row * 32 + lane] = val - m - __logf(sum);
}

// ---------------- launcher ----------------------------------------------------
extern "C" void kernel_launch(void* const* d_in, const int* in_sizes, int n_in,
                              void* d_out, int out_size) {
    const float* x   = (const float*)d_in[0];
    const void*  ei  = d_in[1];
    const float* ew  = (const float*)d_in[2];
    const float* W10 = (const float*)d_in[3];
    const float* W11 = (const float*)d_in[4];
    const float* b1  = (const float*)d_in[5];
    const float* W20 = (const float*)d_in[6];
    const float* W21 = (const float*)d_in[7];
    const float* b2  = (const float*)d_in[8];
    float* out = (float*)d_out;

    int N = in_sizes[0] / 128;
    int E = in_sizes[2];

    k_init<<<(N + 255) / 256, 256>>>((const int*)ei, N);
    k_cnt<<<(E + 255) / 256, 256>>>(ei, E);

    int NB = (N + 2047) / 2048;
    k_scan_local<<<NB, 1024>>>(N);
    k_scan_bsums<<<1, 32>>>(NB);
    k_scan_add<<<(N + 255) / 256, 256>>>(N);

    k_scatter<<<(E + 255) / 256, 256>>>(ei, ew, E);

    k_gemm1<<<(N + 31) / 32, 256>>>(x, W10, W11, N);
    k_layer1<<<(N * 32 + 255) / 256, 256>>>(b1, N);
    k_layer2<<<(N * 32 + 255) / 256, 256>>>(W20, W21, b2, out, N);
}